// round 13
// baseline (speedup 1.0000x reference)
#include <cuda_runtime.h>
#include <cuda_bf16.h>

#define N_NODES 100000
#define N_EDGES 3200000

// Padded positions: one aligned 16B gather per endpoint instead of an
// unaligned 12B load spanning up to two sectors.
__device__ float4 g_pos4[N_NODES];

// Block-split prep: blocks [0, nb_pad) pad positions into g_pos4,
// blocks [nb_pad, 2*nb_pad) zero the accumulator. The two independent
// tasks overlap inside one launch (no per-thread serialization).
__global__ void prep_split_kernel(const float* __restrict__ pos,
                                  float4* __restrict__ out4,
                                  int n, int nb_pad) {
    int b = blockIdx.x;
    if (b < nb_pad) {
        int i = b * blockDim.x + threadIdx.x;
        if (i < n) {
            g_pos4[i] = make_float4(pos[3 * i], pos[3 * i + 1],
                                    pos[3 * i + 2], 0.0f);
        }
    } else {
        int i = (b - nb_pad) * blockDim.x + threadIdx.x;
        if (i < n) {
            out4[i] = make_float4(0.0f, 0.0f, 0.0f, 0.0f);
        }
    }
}

__device__ __forceinline__ void process_edge(int s, int d, float4* out4) {
    float4 ps = __ldg(&g_pos4[s]);
    float4 pd = __ldg(&g_pos4[d]);
    float rx = pd.x - ps.x;
    float ry = pd.y - ps.y;
    float rz = pd.z - ps.z;
    float dot = fmaf(rx, rx, fmaf(ry, ry, rz * rz));
    // rel==0 -> dot==0 -> inv = rsqrt(1e-24) finite, 0*finite = 0 (matches ref)
    float inv = rsqrtf(fmaxf(dot, 1e-24f));
    float x = rx * inv;
    float y = ry * inv;
    float z = rz * inv;
    float* addr = reinterpret_cast<float*>(out4 + d);
    asm volatile("red.global.add.v4.f32 [%0], {%1, %2, %3, %4};"
                 :: "l"(addr), "f"(1.0f), "f"(x), "f"(y), "f"(z)
                 : "memory");
}

// 4 edges per thread via int4 index loads: coalesced 128-bit streams + MLP.
// At the L1tex/L2 wavefront floor: 3 wavefronts/edge (2 gathers + 1 red.v4).
// Best-measured form (R1) -- unchanged.
__global__ void edge_kernel(const int4* __restrict__ src4,
                            const int4* __restrict__ dst4,
                            float4* __restrict__ out4, int n_quads) {
    int t = blockIdx.x * blockDim.x + threadIdx.x;
    if (t >= n_quads) return;
    int4 s = __ldg(src4 + t);
    int4 d = __ldg(dst4 + t);
    process_edge(s.x, d.x, out4);
    process_edge(s.y, d.y, out4);
    process_edge(s.z, d.z, out4);
    process_edge(s.w, d.w, out4);
}

// Best-measured form (R1) -- unchanged.
__global__ void finalize_kernel(const float* __restrict__ node_feat,
                                const float* __restrict__ w0,
                                const float* __restrict__ w1,
                                float4* __restrict__ out4, int n) {
    int i = blockIdx.x * blockDim.x + threadIdx.x;
    if (i < n) {
        float4 a = out4[i];            // {count, sum_shx, sum_shy, sum_shz}
        float cnt = a.x;
        float r = 1.0f / fmaxf(cnt, 1.0f);
        float f = __ldg(&node_feat[i]);
        float w0v = __ldg(&w0[0]);
        float w1x = __ldg(&w1[0]);
        float w1y = __ldg(&w1[1]);
        float w1z = __ldg(&w1[2]);
        float fr = f * r;
        float4 o;
        o.x = w0v * fr * cnt;          // = w0*f when cnt>0, else 0
        o.y = w1x * fr * a.y;
        o.z = w1y * fr * a.z;
        o.w = w1z * fr * a.w;
        out4[i] = o;
    }
}

extern "C" void kernel_launch(void* const* d_in, const int* in_sizes, int n_in,
                              void* d_out, int out_size) {
    const float* positions = (const float*)d_in[0];   // [N,3]
    const float* node_feat = (const float*)d_in[1];   // [N,1]
    const float* w0        = (const float*)d_in[2];   // [1]
    const float* w1        = (const float*)d_in[3];   // [3]
    const int*   edge_src  = (const int*)d_in[4];     // [E]
    const int*   edge_dst  = (const int*)d_in[5];     // [E]

    const int n_nodes = in_sizes[1];        // node_feat count == N
    const int n_edges = in_sizes[4];

    float4* out4 = (float4*)d_out;
    const int B = 256;

    int nb_pad = (n_nodes + B - 1) / B;
    prep_split_kernel<<<2 * nb_pad, B>>>(positions, out4, n_nodes, nb_pad);

    int n_quads = n_edges / 4;   // E = 3,200,000 divisible by 4
    edge_kernel<<<(n_quads + B - 1) / B, B>>>((const int4*)edge_src,
                                              (const int4*)edge_dst,
                                              out4, n_quads);

    finalize_kernel<<<(n_nodes + B - 1) / B, B>>>(node_feat, w0, w1, out4, n_nodes);
}

// round 14
// speedup vs baseline: 1.0066x; 1.0066x over previous
#include <cuda_runtime.h>
#include <cuda_bf16.h>

#define N_NODES 100000
#define N_EDGES 3200000

// Padded positions: one aligned 16B gather per endpoint instead of an
// unaligned 12B load spanning up to two sectors.
__device__ float4 g_pos4[N_NODES];

// Block-split prep: blocks [0, nb_pad) pad positions into g_pos4,
// blocks [nb_pad, 2*nb_pad) zero the accumulator. The two independent
// tasks overlap inside one launch.
__global__ void prep_split_kernel(const float* __restrict__ pos,
                                  float4* __restrict__ out4,
                                  int n, int nb_pad) {
    int b = blockIdx.x;
    if (b < nb_pad) {
        int i = b * blockDim.x + threadIdx.x;
        if (i < n) {
            g_pos4[i] = make_float4(pos[3 * i], pos[3 * i + 1],
                                    pos[3 * i + 2], 0.0f);
        }
    } else {
        int i = (b - nb_pad) * blockDim.x + threadIdx.x;
        if (i < n) {
            out4[i] = make_float4(0.0f, 0.0f, 0.0f, 0.0f);
        }
    }
}

__device__ __forceinline__ void process_edge(int s, int d, float4* out4) {
    float4 ps = __ldg(&g_pos4[s]);
    float4 pd = __ldg(&g_pos4[d]);
    float rx = pd.x - ps.x;
    float ry = pd.y - ps.y;
    float rz = pd.z - ps.z;
    float dot = fmaf(rx, rx, fmaf(ry, ry, rz * rz));
    // rel==0 -> dot==0 -> inv = rsqrt(1e-24) finite, 0*finite = 0 (matches ref)
    float inv = rsqrtf(fmaxf(dot, 1e-24f));
    float x = rx * inv;
    float y = ry * inv;
    float z = rz * inv;
    float* addr = reinterpret_cast<float*>(out4 + d);
    asm volatile("red.global.add.v4.f32 [%0], {%1, %2, %3, %4};"
                 :: "l"(addr), "f"(1.0f), "f"(x), "f"(y), "f"(z)
                 : "memory");
}

// 4 edges per thread via int4 index loads. At the L1tex wavefront floor:
// 3 wavefronts/edge (2 random gathers + 1 red.v4). 128-thread blocks:
// finer scheduling granularity for the wavefront-queue-bound kernel.
__global__ void __launch_bounds__(128)
edge_kernel(const int4* __restrict__ src4,
            const int4* __restrict__ dst4,
            float4* __restrict__ out4, int n_quads) {
    int t = blockIdx.x * blockDim.x + threadIdx.x;
    if (t >= n_quads) return;
    int4 s = __ldg(src4 + t);
    int4 d = __ldg(dst4 + t);
    process_edge(s.x, d.x, out4);
    process_edge(s.y, d.y, out4);
    process_edge(s.z, d.z, out4);
    process_edge(s.w, d.w, out4);
}

// Best-measured form (R1) -- unchanged.
__global__ void finalize_kernel(const float* __restrict__ node_feat,
                                const float* __restrict__ w0,
                                const float* __restrict__ w1,
                                float4* __restrict__ out4, int n) {
    int i = blockIdx.x * blockDim.x + threadIdx.x;
    if (i < n) {
        float4 a = out4[i];            // {count, sum_shx, sum_shy, sum_shz}
        float cnt = a.x;
        float r = 1.0f / fmaxf(cnt, 1.0f);
        float f = __ldg(&node_feat[i]);
        float w0v = __ldg(&w0[0]);
        float w1x = __ldg(&w1[0]);
        float w1y = __ldg(&w1[1]);
        float w1z = __ldg(&w1[2]);
        float fr = f * r;
        float4 o;
        o.x = w0v * fr * cnt;          // = w0*f when cnt>0, else 0
        o.y = w1x * fr * a.y;
        o.z = w1y * fr * a.z;
        o.w = w1z * fr * a.w;
        out4[i] = o;
    }
}

extern "C" void kernel_launch(void* const* d_in, const int* in_sizes, int n_in,
                              void* d_out, int out_size) {
    const float* positions = (const float*)d_in[0];   // [N,3]
    const float* node_feat = (const float*)d_in[1];   // [N,1]
    const float* w0        = (const float*)d_in[2];   // [1]
    const float* w1        = (const float*)d_in[3];   // [3]
    const int*   edge_src  = (const int*)d_in[4];     // [E]
    const int*   edge_dst  = (const int*)d_in[5];     // [E]

    const int n_nodes = in_sizes[1];        // node_feat count == N
    const int n_edges = in_sizes[4];

    float4* out4 = (float4*)d_out;
    const int B = 256;

    int nb_pad = (n_nodes + B - 1) / B;
    prep_split_kernel<<<2 * nb_pad, B>>>(positions, out4, n_nodes, nb_pad);

    int n_quads = n_edges / 4;   // E = 3,200,000 divisible by 4
    edge_kernel<<<(n_quads + 127) / 128, 128>>>((const int4*)edge_src,
                                                (const int4*)edge_dst,
                                                out4, n_quads);

    finalize_kernel<<<(n_nodes + B - 1) / B, B>>>(node_feat, w0, w1, out4, n_nodes);
}